// round 1
// baseline (speedup 1.0000x reference)
#include <cuda_runtime.h>

#define B_ 8
#define T_ 1024
#define E_ 1024
#define H_ 16
#define D_ 64
#define M_ (B_*T_)   // 8192 rows

// Scratch (allocation-free rule: __device__ globals)
__device__ float g_Q[B_*H_*T_*D_];
__device__ float g_K[B_*H_*T_*D_];
__device__ float g_V[B_*H_*T_*D_];
__device__ float g_C[M_*E_];

// ---------------------------------------------------------------------------
// GEMM: Y[m,n] = sum_k X[m,k] * W[n,k] + bias[n]
// X: [M_, E_] row-major, W: [E_, E_] row-major (torch Linear weight, out x in)
// BHTD=1: scatter output to (B,H,T,D) layout for attention. BHTD=0: row-major.
// Tile 128x128xK8, 256 threads, 8x8 per-thread register tile.
// ---------------------------------------------------------------------------
template<int BHTD>
__global__ void __launch_bounds__(256)
gemm_bias(const float* __restrict__ X, const float* __restrict__ W,
          const float* __restrict__ bias, float* __restrict__ Y)
{
    __shared__ float As[8][132];   // stride 132: conflict-free scatter + aligned float4 reads
    __shared__ float Bs[8][132];

    const int tid = threadIdx.x;
    const int tx  = tid & 15;
    const int ty  = tid >> 4;
    const int m0  = blockIdx.y * 128;
    const int n0  = blockIdx.x * 128;

    float acc[8][8];
#pragma unroll
    for (int i = 0; i < 8; ++i)
#pragma unroll
        for (int j = 0; j < 8; ++j) acc[i][j] = 0.f;

    const int lRow = tid >> 1;        // 0..127
    const int lCol = (tid & 1) * 4;   // 0 or 4
    const float* Xp = X + (size_t)(m0 + lRow) * E_ + lCol;
    const float* Wp = W + (size_t)(n0 + lRow) * E_ + lCol;

    for (int k0 = 0; k0 < E_; k0 += 8) {
        float4 av = *(const float4*)(Xp + k0);
        float4 bv = *(const float4*)(Wp + k0);
        As[lCol+0][lRow] = av.x; As[lCol+1][lRow] = av.y;
        As[lCol+2][lRow] = av.z; As[lCol+3][lRow] = av.w;
        Bs[lCol+0][lRow] = bv.x; Bs[lCol+1][lRow] = bv.y;
        Bs[lCol+2][lRow] = bv.z; Bs[lCol+3][lRow] = bv.w;
        __syncthreads();

#pragma unroll
        for (int kk = 0; kk < 8; ++kk) {
            float a[8], b[8];
            float4 t0 = *(const float4*)&As[kk][ty*8];
            float4 t1 = *(const float4*)&As[kk][ty*8+4];
            float4 u0 = *(const float4*)&Bs[kk][tx*8];
            float4 u1 = *(const float4*)&Bs[kk][tx*8+4];
            a[0]=t0.x; a[1]=t0.y; a[2]=t0.z; a[3]=t0.w;
            a[4]=t1.x; a[5]=t1.y; a[6]=t1.z; a[7]=t1.w;
            b[0]=u0.x; b[1]=u0.y; b[2]=u0.z; b[3]=u0.w;
            b[4]=u1.x; b[5]=u1.y; b[6]=u1.z; b[7]=u1.w;
#pragma unroll
            for (int i = 0; i < 8; ++i)
#pragma unroll
                for (int j = 0; j < 8; ++j)
                    acc[i][j] = fmaf(a[i], b[j], acc[i][j]);
        }
        __syncthreads();
    }

#pragma unroll
    for (int i = 0; i < 8; ++i) {
        const int m = m0 + ty*8 + i;
#pragma unroll
        for (int j = 0; j < 8; j += 4) {
            const int n = n0 + tx*8 + j;
            float4 v;
            v.x = acc[i][j+0] + bias[n+0];
            v.y = acc[i][j+1] + bias[n+1];
            v.z = acc[i][j+2] + bias[n+2];
            v.w = acc[i][j+3] + bias[n+3];
            if (BHTD) {
                const int b = m >> 10, t = m & (T_-1);
                const int h = n >> 6,  d = n & 63;
                *(float4*)&Y[((((size_t)b*H_ + h)*T_) + t)*D_ + d] = v;
            } else {
                *(float4*)&Y[(size_t)m*E_ + n] = v;
            }
        }
    }
}

// ---------------------------------------------------------------------------
// Flash-style attention, fp32. One CTA per (bh, 64-row q tile). Bc = 64.
// Threads: 16x16. Thread (tx,ty): S rows ty*4..+3, S cols {tx, tx+16, tx+32, tx+48},
// O cols tx*4..+3. Smem strides: Qs/Ks/Ps = 65 (bank-conflict-free per analysis),
// Vs = 68 (16B-aligned float4 rows).
// ---------------------------------------------------------------------------
__global__ void __launch_bounds__(256)
attn_kernel(const float* __restrict__ Q, const float* __restrict__ K,
            const float* __restrict__ V, float* __restrict__ ctx)
{
    extern __shared__ float sm[];
    float* Qs = sm;               // [64][65]
    float* Ks = sm + 64*65;       // [64][65]
    float* Ps = sm + 2*64*65;     // [64][65]
    float* Vs = sm + 3*64*65;     // [64][68], byte offset 49920 (16B aligned)

    const int tid = threadIdx.x;
    const int tx  = tid & 15;
    const int ty  = tid >> 4;
    const int bh  = blockIdx.y;           // 0..127
    const int q0  = blockIdx.x * 64;

    const float* Qg = Q + ((size_t)bh*T_ + q0) * D_;
    const float* Kg = K + (size_t)bh*T_*D_;
    const float* Vg = V + (size_t)bh*T_*D_;

    // Load Q tile, pre-scaled by 1/sqrt(D)=0.125
#pragma unroll
    for (int i = 0; i < 4; ++i) {
        const int lin = tid + i*256;      // 0..1023
        const int r   = lin >> 4;
        const int c4  = (lin & 15) * 4;
        float4 v = *(const float4*)(Qg + r*D_ + c4);
        Qs[r*65 + c4+0] = v.x * 0.125f;
        Qs[r*65 + c4+1] = v.y * 0.125f;
        Qs[r*65 + c4+2] = v.z * 0.125f;
        Qs[r*65 + c4+3] = v.w * 0.125f;
    }

    float m_i[4], l_i[4], acc[4][4];
#pragma unroll
    for (int i = 0; i < 4; ++i) {
        m_i[i] = -1e30f; l_i[i] = 0.f;
#pragma unroll
        for (int j = 0; j < 4; ++j) acc[i][j] = 0.f;
    }

    for (int kt = 0; kt < T_; kt += 64) {
        __syncthreads();   // previous iteration's readers done
        // Load K and V tiles (coalesced float4)
#pragma unroll
        for (int i = 0; i < 4; ++i) {
            const int lin = tid + i*256;
            const int r   = lin >> 4;
            const int c4  = (lin & 15) * 4;
            float4 kv = *(const float4*)(Kg + (size_t)(kt + r)*D_ + c4);
            Ks[r*65 + c4+0] = kv.x; Ks[r*65 + c4+1] = kv.y;
            Ks[r*65 + c4+2] = kv.z; Ks[r*65 + c4+3] = kv.w;
            float4 vv = *(const float4*)(Vg + (size_t)(kt + r)*D_ + c4);
            *(float4*)&Vs[r*68 + c4] = vv;
        }
        __syncthreads();

        // S = (Q/8) K^T : 4x4 per thread
        float s[4][4];
#pragma unroll
        for (int i = 0; i < 4; ++i)
#pragma unroll
            for (int j = 0; j < 4; ++j) s[i][j] = 0.f;

#pragma unroll 8
        for (int d = 0; d < 64; ++d) {
            float a0 = Qs[(ty*4+0)*65 + d];
            float a1 = Qs[(ty*4+1)*65 + d];
            float a2 = Qs[(ty*4+2)*65 + d];
            float a3 = Qs[(ty*4+3)*65 + d];
            float b0 = Ks[(tx +  0)*65 + d];
            float b1 = Ks[(tx + 16)*65 + d];
            float b2 = Ks[(tx + 32)*65 + d];
            float b3 = Ks[(tx + 48)*65 + d];
            s[0][0] = fmaf(a0,b0,s[0][0]); s[0][1] = fmaf(a0,b1,s[0][1]);
            s[0][2] = fmaf(a0,b2,s[0][2]); s[0][3] = fmaf(a0,b3,s[0][3]);
            s[1][0] = fmaf(a1,b0,s[1][0]); s[1][1] = fmaf(a1,b1,s[1][1]);
            s[1][2] = fmaf(a1,b2,s[1][2]); s[1][3] = fmaf(a1,b3,s[1][3]);
            s[2][0] = fmaf(a2,b0,s[2][0]); s[2][1] = fmaf(a2,b1,s[2][1]);
            s[2][2] = fmaf(a2,b2,s[2][2]); s[2][3] = fmaf(a2,b3,s[2][3]);
            s[3][0] = fmaf(a3,b0,s[3][0]); s[3][1] = fmaf(a3,b1,s[3][1]);
            s[3][2] = fmaf(a3,b2,s[3][2]); s[3][3] = fmaf(a3,b3,s[3][3]);
        }

        // Online softmax per row (row owned by 16 tx-lanes; shfl-xor within 16)
#pragma unroll
        for (int i = 0; i < 4; ++i) {
            float mx = fmaxf(fmaxf(s[i][0], s[i][1]), fmaxf(s[i][2], s[i][3]));
            mx = fmaxf(mx, __shfl_xor_sync(0xffffffffu, mx, 8));
            mx = fmaxf(mx, __shfl_xor_sync(0xffffffffu, mx, 4));
            mx = fmaxf(mx, __shfl_xor_sync(0xffffffffu, mx, 2));
            mx = fmaxf(mx, __shfl_xor_sync(0xffffffffu, mx, 1));
            const float mnew  = fmaxf(m_i[i], mx);
            const float alpha = __expf(m_i[i] - mnew);
            m_i[i] = mnew;
            float rs = 0.f;
#pragma unroll
            for (int j = 0; j < 4; ++j) { s[i][j] = __expf(s[i][j] - mnew); rs += s[i][j]; }
            rs += __shfl_xor_sync(0xffffffffu, rs, 8);
            rs += __shfl_xor_sync(0xffffffffu, rs, 4);
            rs += __shfl_xor_sync(0xffffffffu, rs, 2);
            rs += __shfl_xor_sync(0xffffffffu, rs, 1);
            l_i[i] = l_i[i]*alpha + rs;
#pragma unroll
            for (int j = 0; j < 4; ++j) acc[i][j] *= alpha;
        }

        // Stage P to smem
#pragma unroll
        for (int i = 0; i < 4; ++i)
#pragma unroll
            for (int j = 0; j < 4; ++j)
                Ps[(ty*4+i)*65 + tx + 16*j] = s[i][j];
        __syncthreads();

        // O += P @ V
#pragma unroll 8
        for (int c = 0; c < 64; ++c) {
            float p0 = Ps[(ty*4+0)*65 + c];
            float p1 = Ps[(ty*4+1)*65 + c];
            float p2 = Ps[(ty*4+2)*65 + c];
            float p3 = Ps[(ty*4+3)*65 + c];
            float4 vv = *(const float4*)&Vs[c*68 + tx*4];
            acc[0][0] = fmaf(p0,vv.x,acc[0][0]); acc[0][1] = fmaf(p0,vv.y,acc[0][1]);
            acc[0][2] = fmaf(p0,vv.z,acc[0][2]); acc[0][3] = fmaf(p0,vv.w,acc[0][3]);
            acc[1][0] = fmaf(p1,vv.x,acc[1][0]); acc[1][1] = fmaf(p1,vv.y,acc[1][1]);
            acc[1][2] = fmaf(p1,vv.z,acc[1][2]); acc[1][3] = fmaf(p1,vv.w,acc[1][3]);
            acc[2][0] = fmaf(p2,vv.x,acc[2][0]); acc[2][1] = fmaf(p2,vv.y,acc[2][1]);
            acc[2][2] = fmaf(p2,vv.z,acc[2][2]); acc[2][3] = fmaf(p2,vv.w,acc[2][3]);
            acc[3][0] = fmaf(p3,vv.x,acc[3][0]); acc[3][1] = fmaf(p3,vv.y,acc[3][1]);
            acc[3][2] = fmaf(p3,vv.z,acc[3][2]); acc[3][3] = fmaf(p3,vv.w,acc[3][3]);
        }
    }

    // Write ctx in (B, T, E) layout: ctx[b, t, h*64 + d]
    const int b = bh >> 4;
    const int h = bh & 15;
#pragma unroll
    for (int i = 0; i < 4; ++i) {
        const float inv = 1.f / l_i[i];
        const int t = q0 + ty*4 + i;
        float4 o;
        o.x = acc[i][0]*inv; o.y = acc[i][1]*inv;
        o.z = acc[i][2]*inv; o.w = acc[i][3]*inv;
        *(float4*)&ctx[((size_t)b*T_ + t)*E_ + h*64 + tx*4] = o;
    }
}

// ---------------------------------------------------------------------------
extern "C" void kernel_launch(void* const* d_in, const int* in_sizes, int n_in,
                              void* d_out, int out_size)
{
    const float* query = (const float*)d_in[0];
    const float* key   = (const float*)d_in[1];
    const float* value = (const float*)d_in[2];
    const float* Wq = (const float*)d_in[3];  const float* bq = (const float*)d_in[4];
    const float* Wk = (const float*)d_in[5];  const float* bk = (const float*)d_in[6];
    const float* Wv = (const float*)d_in[7];  const float* bv = (const float*)d_in[8];
    const float* Wo = (const float*)d_in[9];  const float* bo = (const float*)d_in[10];
    float* out = (float*)d_out;

    float *Qb, *Kb, *Vb, *Cb;
    cudaGetSymbolAddress((void**)&Qb, g_Q);
    cudaGetSymbolAddress((void**)&Kb, g_K);
    cudaGetSymbolAddress((void**)&Vb, g_V);
    cudaGetSymbolAddress((void**)&Cb, g_C);

    const dim3 gGrid(E_/128, M_/128);   // (8, 64)

    gemm_bias<1><<<gGrid, 256>>>(query, Wq, bq, Qb);
    gemm_bias<1><<<gGrid, 256>>>(key,   Wk, bk, Kb);
    gemm_bias<1><<<gGrid, 256>>>(value, Wv, bv, Vb);

    const int attn_smem = (3*64*65 + 64*68) * (int)sizeof(float);   // 67328 B
    cudaFuncSetAttribute(attn_kernel, cudaFuncAttributeMaxDynamicSharedMemorySize, attn_smem);
    attn_kernel<<<dim3(T_/64, B_*H_), 256, attn_smem>>>(Qb, Kb, Vb, Cb);

    gemm_bias<0><<<gGrid, 256>>>(Cb, Wo, bo, out);
}